// round 7
// baseline (speedup 1.0000x reference)
#include <cuda_runtime.h>
#include <math.h>

// Problem constants (fixed by the reference).
#define BB 8
#define CC 16
#define NNDIM 512
#define EE 1024
#define POS_PER_B  (NNDIM * NNDIM)        // 262,144
#define GRID_ELEMS (BB * POS_PER_B)       // 2,097,152
#define NGROUPS (GRID_ELEMS / 4)          // 524,288 float4 groups
#define PBLK 444                          // persistent: 148 SMs * 3 blocks
#define HASH_SZ 4096

// Accumulators (no dynamic allocation allowed).
__device__ double g_sum[BB];
__device__ double g_cnt[BB];
__device__ unsigned int g_done;

// ---------------------------------------------------------------------------
// 1) Correction kernel: one block per batch, one thread per edge.
//    Zeroes accumulators; exact last-write-wins dedup via O(E) shared hash
//    (atomicCAS slot claim + atomicMax edge index); accumulates
//    (x_class0 - x_attr) for live, nonzero-attr, masked-valid edges.
// ---------------------------------------------------------------------------
__global__ void __launch_bounds__(EE) corr_kernel(
        const float* __restrict__ adj,
        const unsigned char* __restrict__ mask,
        const int* __restrict__ edge_index,
        const int* __restrict__ edge_attr) {
    __shared__ int s_slotkey[HASH_SZ];
    __shared__ int s_slotval[HASH_SZ];
    const int b = blockIdx.x;
    const int e = threadIdx.x;               // 0..EE-1

    if (e == 0) {
        g_sum[b] = 0.0;
        g_cnt[b] = 0.0;
        if (b == 0) g_done = 0u;
    }
    #pragma unroll
    for (int i = e; i < HASH_SZ; i += EE) {
        s_slotkey[i] = -1;
        s_slotval[i] = -1;
    }

    const int2 rc  = reinterpret_cast<const int2*>(edge_index)[(size_t)b * EE + e];
    const int key  = (rc.x << 9) | rc.y;     // r, c in [0, 512)
    const int attr = edge_attr[b * EE + e];
    __syncthreads();

    unsigned h = (((unsigned)key * 2654435761u) >> 20) & (HASH_SZ - 1);
    while (true) {
        int old = atomicCAS(&s_slotkey[h], -1, key);
        if (old == -1 || old == key) { atomicMax(&s_slotval[h], e); break; }
        h = (h + 1) & (HASH_SZ - 1);
    }
    __syncthreads();

    const bool live = (s_slotval[h] == e);   // last scatter write wins

    float corr = 0.0f;
    if (live && attr != 0) {
        const size_t cell = (size_t)b * POS_PER_B + (size_t)rc.x * NNDIM + rc.y;
        if (mask[cell]) {
            const float* p = adj + (size_t)b * CC * POS_PER_B
                           + (size_t)rc.x * NNDIM + rc.y;
            corr = p[0] - p[(size_t)attr * POS_PER_B];   // swap x_0 -> x_attr
        }
    }

    #pragma unroll
    for (int off = 16; off > 0; off >>= 1)
        corr += __shfl_down_sync(0xFFFFFFFFu, corr, off);
    __shared__ float r_sum[32];
    const int lane = e & 31, warp = e >> 5;
    if (lane == 0) r_sum[warp] = corr;
    __syncthreads();
    if (warp == 0) {
        float v = r_sum[lane];
        #pragma unroll
        for (int off = 16; off > 0; off >>= 1)
            v += __shfl_down_sync(0xFFFFFFFFu, v, off);
        if (lane == 0) atomicAdd(&g_sum[b], (double)v);
    }
}

// ---------------------------------------------------------------------------
// 2) Persistent streaming loss kernel: 444 blocks, grid-stride loop.
//    Each iteration: one thread = 4 consecutive positions; all 16 class
//    float4 loads staged into registers (MLP_p1=16, evict-first via __ldcs),
//    then exp/accumulate, then block-reduce + per-batch atomic.
//    Each 256-group iteration chunk lies in one batch (2^16 | 256-aligned).
//    Last retiring block (ticket) computes the final batch-mean scalar.
// ---------------------------------------------------------------------------
__global__ void __launch_bounds__(256, 3) loss_kernel(
        const float* __restrict__ adj,
        const unsigned char* __restrict__ mask,
        float* __restrict__ out) {
    const int t    = threadIdx.x;
    const int lane = t & 31, warp = t >> 5;
    __shared__ float r_sum[8];
    __shared__ float r_cnt[8];

    for (int idx4 = blockIdx.x * 256 + t; idx4 < NGROUPS; idx4 += PBLK * 256) {
        const int b   = idx4 >> 16;                   // 65536 float4 per batch
        const int pos = (idx4 << 2) & (POS_PER_B - 1);

        const float4* base = reinterpret_cast<const float4*>(
            adj + (size_t)b * CC * POS_PER_B + pos);
        const uchar4 m4 =
            *reinterpret_cast<const uchar4*>(mask + ((size_t)idx4 << 2));

        // ---- phase 1: batched loads (16 independent LDG.128) ----
        float4 v[CC];
        #pragma unroll
        for (int c = 0; c < CC; c++)
            v[c] = __ldcs(base + (size_t)c * (POS_PER_B / 4));

        // ---- phase 2: exp / accumulate ----
        float s0 = __expf(v[0].x), s1 = __expf(v[0].y);
        float s2 = __expf(v[0].z), s3 = __expf(v[0].w);
        #pragma unroll
        for (int c = 1; c < CC; c++) {
            s0 += __expf(v[c].x); s1 += __expf(v[c].y);
            s2 += __expf(v[c].z); s3 += __expf(v[c].w);
        }

        float sum = 0.0f, cnt = 0.0f;
        if (m4.x) { sum += __logf(s0) - v[0].x; cnt += 1.0f; }
        if (m4.y) { sum += __logf(s1) - v[0].y; cnt += 1.0f; }
        if (m4.z) { sum += __logf(s2) - v[0].z; cnt += 1.0f; }
        if (m4.w) { sum += __logf(s3) - v[0].w; cnt += 1.0f; }

        // ---- block reduction for this iteration (single batch b) ----
        #pragma unroll
        for (int off = 16; off > 0; off >>= 1) {
            sum += __shfl_down_sync(0xFFFFFFFFu, sum, off);
            cnt += __shfl_down_sync(0xFFFFFFFFu, cnt, off);
        }
        if (lane == 0) { r_sum[warp] = sum; r_cnt[warp] = cnt; }
        __syncthreads();
        if (t == 0) {
            float bs = 0.0f, bc = 0.0f;
            #pragma unroll
            for (int w = 0; w < 8; w++) { bs += r_sum[w]; bc += r_cnt[w]; }
            atomicAdd(&g_sum[b], (double)bs);
            atomicAdd(&g_cnt[b], (double)bc);
        }
        __syncthreads();   // protect r_sum/r_cnt reuse next iteration
    }

    // ---- retire: last block finalizes ----
    if (t == 0) {
        __threadfence();
        const unsigned ticket = atomicAdd(&g_done, 1u);
        if (ticket == PBLK - 1) {
            double acc = 0.0;
            #pragma unroll
            for (int i = 0; i < BB; i++) {
                volatile double* vs = g_sum;
                volatile double* vc = g_cnt;
                double c = vc[i];
                if (c < 1.0) c = 1.0;
                acc += vs[i] / c;
            }
            out[0] = (float)(acc / (double)BB);
        }
    }
}

// ---------------------------------------------------------------------------
// kernel_launch — inputs (metadata order): adj f32 [B,C,N,N], mask bool(u8)
// [B,N,N], edge_index i32 [B,E,2], edge_attr i32 [B,E]. Output: 1 fp32 scalar.
// ---------------------------------------------------------------------------
extern "C" void kernel_launch(void* const* d_in, const int* in_sizes, int n_in,
                              void* d_out, int out_size) {
    const float*         adj        = (const float*)d_in[0];
    const unsigned char* mask       = (const unsigned char*)d_in[1];
    const int*           edge_index = (const int*)d_in[2];
    const int*           edge_attr  = (const int*)d_in[3];
    float*               out        = (float*)d_out;

    corr_kernel<<<BB, EE>>>(adj, mask, edge_index, edge_attr);
    loss_kernel<<<PBLK, 256>>>(adj, mask, out);
}

// round 8
// speedup vs baseline: 1.0586x; 1.0586x over previous
#include <cuda_runtime.h>
#include <math.h>

// Problem constants (fixed by the reference).
#define BB 8
#define CC 16
#define NNDIM 512
#define EE 1024
#define POS_PER_B   (NNDIM * NNDIM)       // 262,144
#define GRID_ELEMS  (BB * POS_PER_B)      // 2,097,152
#define GROUPS_PER_B (POS_PER_B / 4)      // 65,536 float4 groups per batch
#define CHUNKS_PER_B (GROUPS_PER_B / 256) // 256 chunks of 256 groups
#define PBLK 444                          // persistent: 148 SMs * 3 blocks
#define HASH_SZ 4096

// Globals (no dynamic allocation allowed).
__device__ double g_sum[BB];
__device__ double g_cnt[BB];
__device__ unsigned int g_done;
__device__ unsigned int g_chunk[BB];      // per-batch dynamic chunk counters

// ---------------------------------------------------------------------------
// 1) Correction kernel: one block per batch, one thread per edge.
//    Zeroes accumulators + chunk counters; exact last-write-wins dedup via
//    O(E) shared hash; accumulates (x_class0 - x_attr) for live, nonzero-attr,
//    masked-valid edges into g_sum[b].
// ---------------------------------------------------------------------------
__global__ void __launch_bounds__(EE) corr_kernel(
        const float* __restrict__ adj,
        const unsigned char* __restrict__ mask,
        const int* __restrict__ edge_index,
        const int* __restrict__ edge_attr) {
    __shared__ int s_slotkey[HASH_SZ];
    __shared__ int s_slotval[HASH_SZ];
    const int b = blockIdx.x;
    const int e = threadIdx.x;               // 0..EE-1

    if (e == 0) {
        g_sum[b] = 0.0;
        g_cnt[b] = 0.0;
        g_chunk[b] = 0u;
        if (b == 0) g_done = 0u;
    }
    #pragma unroll
    for (int i = e; i < HASH_SZ; i += EE) {
        s_slotkey[i] = -1;
        s_slotval[i] = -1;
    }

    const int2 rc  = reinterpret_cast<const int2*>(edge_index)[(size_t)b * EE + e];
    const int key  = (rc.x << 9) | rc.y;     // r, c in [0, 512)
    const int attr = edge_attr[b * EE + e];
    __syncthreads();

    unsigned h = (((unsigned)key * 2654435761u) >> 20) & (HASH_SZ - 1);
    while (true) {
        int old = atomicCAS(&s_slotkey[h], -1, key);
        if (old == -1 || old == key) { atomicMax(&s_slotval[h], e); break; }
        h = (h + 1) & (HASH_SZ - 1);
    }
    __syncthreads();

    const bool live = (s_slotval[h] == e);   // last scatter write wins

    float corr = 0.0f;
    if (live && attr != 0) {
        const size_t cell = (size_t)b * POS_PER_B + (size_t)rc.x * NNDIM + rc.y;
        if (mask[cell]) {
            const float* p = adj + (size_t)b * CC * POS_PER_B
                           + (size_t)rc.x * NNDIM + rc.y;
            corr = p[0] - p[(size_t)attr * POS_PER_B];   // swap x_0 -> x_attr
        }
    }

    #pragma unroll
    for (int off = 16; off > 0; off >>= 1)
        corr += __shfl_down_sync(0xFFFFFFFFu, corr, off);
    __shared__ float r_sum[32];
    const int lane = e & 31, warp = e >> 5;
    if (lane == 0) r_sum[warp] = corr;
    __syncthreads();
    if (warp == 0) {
        float v = r_sum[lane];
        #pragma unroll
        for (int off = 16; off > 0; off >>= 1)
            v += __shfl_down_sync(0xFFFFFFFFu, v, off);
        if (lane == 0) atomicAdd(&g_sum[b], (double)v);
    }
}

// ---------------------------------------------------------------------------
// 2) Persistent streaming loss kernel, per-batch dynamic chunking.
//    Block -> batch b = blockIdx.x & 7. Chunks (256 float4-groups each) are
//    claimed from g_chunk[b]; the next chunk id is PREFETCHED during compute
//    so the atomic latency is hidden. Per thread: 16 class float4 loads staged
//    in registers (MLP_p1=16, __ldcs evict-first), exp/log-sum-exp with label
//    0, accumulate sum/cnt in registers across ALL iterations; single block
//    reduction + RED at retirement. Last block (ticket) finalizes.
// ---------------------------------------------------------------------------
__global__ void __launch_bounds__(256, 3) loss_kernel(
        const float* __restrict__ adj,
        const unsigned char* __restrict__ mask,
        float* __restrict__ out) {
    const int t = threadIdx.x;
    const int b = blockIdx.x & (BB - 1);
    __shared__ int s_next;
    __shared__ float r_sum[8];
    __shared__ float r_cnt[8];

    const float* adj_b  = adj + (size_t)b * CC * POS_PER_B;
    const unsigned char* mask_b = mask + (size_t)b * POS_PER_B;

    float sum = 0.0f, cnt = 0.0f;

    if (t == 0) s_next = (int)atomicAdd(&g_chunk[b], 1u);
    __syncthreads();

    while (true) {
        const int chunk = s_next;
        __syncthreads();                      // all read before overwrite
        if (chunk >= CHUNKS_PER_B) break;
        if (t == 0) s_next = (int)atomicAdd(&g_chunk[b], 1u);  // prefetch

        const int g4  = chunk * 256 + t;      // group index within batch
        const int pos = g4 << 2;

        const float4* base = reinterpret_cast<const float4*>(adj_b + pos);
        const uchar4 m4 = *reinterpret_cast<const uchar4*>(mask_b + pos);

        // ---- phase 1: batched loads (16 independent LDG.128) ----
        float4 v[CC];
        #pragma unroll
        for (int c = 0; c < CC; c++)
            v[c] = __ldcs(base + (size_t)c * (POS_PER_B / 4));

        // ---- phase 2: exp / accumulate ----
        float s0 = __expf(v[0].x), s1 = __expf(v[0].y);
        float s2 = __expf(v[0].z), s3 = __expf(v[0].w);
        #pragma unroll
        for (int c = 1; c < CC; c++) {
            s0 += __expf(v[c].x); s1 += __expf(v[c].y);
            s2 += __expf(v[c].z); s3 += __expf(v[c].w);
        }
        if (m4.x) { sum += __logf(s0) - v[0].x; cnt += 1.0f; }
        if (m4.y) { sum += __logf(s1) - v[0].y; cnt += 1.0f; }
        if (m4.z) { sum += __logf(s2) - v[0].z; cnt += 1.0f; }
        if (m4.w) { sum += __logf(s3) - v[0].w; cnt += 1.0f; }

        __syncthreads();                      // s_next write visible to all
    }

    // ---- single retirement reduction (batch b) ----
    #pragma unroll
    for (int off = 16; off > 0; off >>= 1) {
        sum += __shfl_down_sync(0xFFFFFFFFu, sum, off);
        cnt += __shfl_down_sync(0xFFFFFFFFu, cnt, off);
    }
    const int lane = t & 31, warp = t >> 5;
    if (lane == 0) { r_sum[warp] = sum; r_cnt[warp] = cnt; }
    __syncthreads();

    if (t == 0) {
        float bs = 0.0f, bc = 0.0f;
        #pragma unroll
        for (int w = 0; w < 8; w++) { bs += r_sum[w]; bc += r_cnt[w]; }
        atomicAdd(&g_sum[b], (double)bs);
        atomicAdd(&g_cnt[b], (double)bc);

        __threadfence();
        const unsigned ticket = atomicAdd(&g_done, 1u);
        if (ticket == PBLK - 1) {
            double acc = 0.0;
            #pragma unroll
            for (int i = 0; i < BB; i++) {
                volatile double* vs = g_sum;
                volatile double* vc = g_cnt;
                double c = vc[i];
                if (c < 1.0) c = 1.0;
                acc += vs[i] / c;
            }
            out[0] = (float)(acc / (double)BB);
        }
    }
}

// ---------------------------------------------------------------------------
// kernel_launch — inputs (metadata order): adj f32 [B,C,N,N], mask bool(u8)
// [B,N,N], edge_index i32 [B,E,2], edge_attr i32 [B,E]. Output: 1 fp32 scalar.
// ---------------------------------------------------------------------------
extern "C" void kernel_launch(void* const* d_in, const int* in_sizes, int n_in,
                              void* d_out, int out_size) {
    const float*         adj        = (const float*)d_in[0];
    const unsigned char* mask       = (const unsigned char*)d_in[1];
    const int*           edge_index = (const int*)d_in[2];
    const int*           edge_attr  = (const int*)d_in[3];
    float*               out        = (float*)d_out;

    corr_kernel<<<BB, EE>>>(adj, mask, edge_index, edge_attr);
    loss_kernel<<<PBLK, 256>>>(adj, mask, out);
}